// round 15
// baseline (speedup 1.0000x reference)
#include <cuda_runtime.h>
#include <cuda_fp16.h>
#include <cstdint>

// Problem constants
#define E_DIM   1024
#define N_HEADS 16
#define HDIM    64
#define NB      4
#define SEQ     2048
#define BH_TOT  (NB * N_HEADS)   // 64
#define M_ROWS  (NB * SEQ)       // 8192
#define QKV_PAIRS (BH_TOT * SEQ * HDIM / 2)   // 4194304
#define QSCALE 0.18033688011112042f           // 0.125 * log2(e)

// Scratch (device globals). fp16x2-pair planes.
__device__ uint32_t g_ah[M_ROWS * E_DIM / 2], g_al[M_ROWS * E_DIM / 2];  // query
__device__ uint32_t g_wh[3 * E_DIM * E_DIM / 2];                          // in_w hi
__device__ uint32_t g_oh[E_DIM * E_DIM / 2];                              // out_w hi
__device__ uint32_t g_ch[M_ROWS * E_DIM / 2], g_cl[M_ROWS * E_DIM / 2];  // ctx
__device__ uint32_t g_qh[QKV_PAIRS], g_ql[QKV_PAIRS];
__device__ uint32_t g_kh[QKV_PAIRS];                                      // K hi
__device__ uint32_t g_vh[QKV_PAIRS];                                      // V hi

// ---- helpers ---------------------------------------------------------------
__device__ __forceinline__ uint32_t smem_u32(const void* p) {
    uint32_t a;
    asm("{ .reg .u64 t; cvta.to.shared.u64 t, %1; cvt.u32.u64 %0, t; }"
        : "=r"(a) : "l"(p));
    return a;
}
__device__ __forceinline__ uint32_t h2pack(float e0, float e1) {
    __half2 h = __floats2half2_rn(e0, e1);
    return *reinterpret_cast<uint32_t*>(&h);
}
__device__ __forceinline__ float h_lo(uint32_t p) {
    return __half2float(__ushort_as_half((unsigned short)(p & 0xffffu)));
}
__device__ __forceinline__ float h_hi(uint32_t p) {
    return __half2float(__ushort_as_half((unsigned short)(p >> 16)));
}

__device__ __forceinline__ void cp16(uint32_t dst, const void* src) {
    asm volatile("cp.async.cg.shared.global [%0], [%1], 16;"
                 :: "r"(dst), "l"(src) : "memory");
}
#define CP_COMMIT asm volatile("cp.async.commit_group;" ::: "memory")
#define CP_WAIT0  asm volatile("cp.async.wait_group 0;" ::: "memory")

#define LDSM_X4(r0, r1, r2, r3, addr)                                        \
    asm volatile("ldmatrix.sync.aligned.m8n8.x4.shared.b16 "                 \
                 "{%0, %1, %2, %3}, [%4];"                                   \
                 : "=r"(r0), "=r"(r1), "=r"(r2), "=r"(r3) : "r"(addr))

#define LDSM_X4_T(r0, r1, r2, r3, addr)                                      \
    asm volatile("ldmatrix.sync.aligned.m8n8.x4.trans.shared.b16 "           \
                 "{%0, %1, %2, %3}, [%4];"                                   \
                 : "=r"(r0), "=r"(r1), "=r"(r2), "=r"(r3) : "r"(addr))

// fp32-accumulator fp16 MMA
#define MMA_F16(c, a, b)                                                     \
    asm volatile("mma.sync.aligned.m16n8k16.row.col.f32.f16.f16.f32 "        \
                 "{%0, %1, %2, %3}, {%4, %5, %6, %7}, {%8, %9}, "            \
                 "{%0, %1, %2, %3};"                                         \
                 : "+f"((c)[0]), "+f"((c)[1]), "+f"((c)[2]), "+f"((c)[3])    \
                 : "r"((a)[0]), "r"((a)[1]), "r"((a)[2]), "r"((a)[3]),       \
                   "r"((b)[0]), "r"((b)[1]))

// fp16-accumulator fp16 MMA (full-rate path; used for lo-pass only)
#define MMA_F16ACC(c, a, b)                                                  \
    asm volatile("mma.sync.aligned.m16n8k16.row.col.f16.f16.f16.f16 "        \
                 "{%0, %1}, {%2, %3, %4, %5}, {%6, %7}, {%0, %1};"           \
                 : "+r"((c)[0]), "+r"((c)[1])                                \
                 : "r"((a)[0]), "r"((a)[1]), "r"((a)[2]), "r"((a)[3]),       \
                   "r"((b)[0]), "r"((b)[1]))

// ===========================================================================
// One-pass fp32 -> fp16 split.  which 0: query (hi+lo)  1: in_w (hi)  2: out_w (hi)
// ===========================================================================
__global__ __launch_bounds__(256) void conv_split(const float4* __restrict__ src,
                                                  int which, int n4)
{
    int i = blockIdx.x * 256 + threadIdx.x;
    if (i >= n4) return;
    float4 a = src[i];
    uint32_t h01 = h2pack(a.x, a.y), h23 = h2pack(a.z, a.w);
    if (which == 0) {
        ((uint2*)g_ah)[i] = make_uint2(h01, h23);
        uint32_t l01 = h2pack(a.x - h_lo(h01), a.y - h_hi(h01));
        uint32_t l23 = h2pack(a.z - h_lo(h23), a.w - h_hi(h23));
        ((uint2*)g_al)[i] = make_uint2(l01, l23);
    } else if (which == 1) {
        ((uint2*)g_wh)[i] = make_uint2(h01, h23);
    } else {
        ((uint2*)g_oh)[i] = make_uint2(h01, h23);
    }
}

// ===========================================================================
// fp16x2 tensor-core NT GEMM: hi-pass fp32-acc + lo-pass fp16-acc (combined
// at epilogue; lo contributes ~2^-11 so fp16 acc adds ~2^-22 — negligible).
// A-fragments reused across the hi->lo passes to hold register count.
// which 0: A=g_ah/al, W=g_wh, QKV-scatter epilogue (q *= QSCALE)
// which 1: A=g_ch/cl, W=g_oh, C-store epilogue
// ===========================================================================
#define SROW 40                        // f16 per smem row (32 data + 8 pad)
#define GPLANE (128 * SROW * 2)        // 10240 B
#define GSTAGE (3 * GPLANE)            // 30720 B  (A_hi, A_lo, B_hi)
#define GEMM_SMEM2 (2 * GSTAGE)        // 61440 B

__global__ __launch_bounds__(256, 2) void gemm_v2(
    const float* __restrict__ bias, float* __restrict__ C,
    int K, int N, int which)
{
    extern __shared__ char smraw[];
    uint32_t sbase = smem_u32(smraw);

    const uint4* Ah = (const uint4*)(which == 0 ? g_ah : g_ch);
    const uint4* Al = (const uint4*)(which == 0 ? g_al : g_cl);
    const uint4* Wh = (const uint4*)(which == 0 ? g_wh : g_oh);

    int t    = threadIdx.x;
    int lane = t & 31;
    int wid  = t >> 5;
    int wm   = wid >> 2;
    int wn   = wid & 3;
    int gid  = lane >> 2;
    int tig  = lane & 3;

    int rbase = blockIdx.y * 128;
    int cbase = blockIdx.x * 128;
    int kd8   = K >> 3;

    size_t asi[2], wsi[2];
    uint32_t dso[2];
#pragma unroll
    for (int half = 0; half < 2; half++) {
        int g = t + 256 * half;        // 0..511
        int row = g >> 2, c = g & 3;
        asi[half] = (size_t)(rbase + row) * kd8 + c;
        wsi[half] = (size_t)(cbase + row) * kd8 + c;
        dso[half] = (uint32_t)(row * SROW * 2 + c * 16);
    }

    uint32_t lm_off = (uint32_t)((lane & 15) * SROW + ((lane >> 4) << 3)) * 2;

    float acc[4][4][4];          // hi-pass, fp32 acc
    uint32_t accL[4][4][2];      // lo-pass, fp16 acc (f16x2 pairs)
#pragma unroll
    for (int i = 0; i < 4; i++)
#pragma unroll
        for (int j = 0; j < 4; j++) {
#pragma unroll
            for (int r = 0; r < 4; r++) acc[i][j][r] = 0.f;
            accL[i][j][0] = 0u; accL[i][j][1] = 0u;
        }

    const int nch = K / 32;

#pragma unroll
    for (int half = 0; half < 2; half++) {
        uint32_t d = sbase + dso[half];
        cp16(d + 0 * GPLANE, Ah + asi[half]);
        cp16(d + 1 * GPLANE, Al + asi[half]);
        cp16(d + 2 * GPLANE, Wh + wsi[half]);
    }
    CP_COMMIT;

    for (int ch = 0; ch < nch; ch++) {
        CP_WAIT0;
        __syncthreads();

        if (ch + 1 < nch) {
            uint32_t nb = sbase + ((ch + 1) & 1) * GSTAGE;
#pragma unroll
            for (int half = 0; half < 2; half++) {
                size_t sa = asi[half] + (size_t)(ch + 1) * 4;
                size_t sw = wsi[half] + (size_t)(ch + 1) * 4;
                uint32_t d = nb + dso[half];
                cp16(d + 0 * GPLANE, Ah + sa);
                cp16(d + 1 * GPLANE, Al + sa);
                cp16(d + 2 * GPLANE, Wh + sw);
            }
            CP_COMMIT;
        }

        uint32_t stb  = sbase + (ch & 1) * GSTAGE;
        uint32_t aHiB = stb + (uint32_t)(wm * 64 * SROW * 2) + lm_off;
        uint32_t aLoB = aHiB + GPLANE;
        uint32_t bHiB = stb + 2 * GPLANE + (uint32_t)(wn * 32 * SROW * 2) + lm_off;

#pragma unroll
        for (int kk = 0; kk < 2; kk++) {
            uint32_t kb = (uint32_t)(kk * 16 * 2);
            uint32_t Af[4][4], Bh[4][2];
#pragma unroll
            for (int nt2 = 0; nt2 < 2; nt2++) {
                uint32_t off = kb + (uint32_t)(nt2 * 16 * SROW * 2);
                uint32_t r0, r1, r2, r3;
                LDSM_X4(r0, r1, r2, r3, bHiB + off);
                Bh[nt2 * 2][0] = r0; Bh[nt2 * 2 + 1][0] = r1;
                Bh[nt2 * 2][1] = r2; Bh[nt2 * 2 + 1][1] = r3;
            }
            // hi pass (fp32 acc)
#pragma unroll
            for (int mt = 0; mt < 4; mt++) {
                uint32_t off = kb + (uint32_t)(mt * 16 * SROW * 2);
                LDSM_X4(Af[mt][0], Af[mt][1], Af[mt][2], Af[mt][3], aHiB + off);
            }
#pragma unroll
            for (int mt = 0; mt < 4; mt++)
#pragma unroll
                for (int nt = 0; nt < 4; nt++)
                    MMA_F16(acc[mt][nt], Af[mt], Bh[nt]);
            // lo pass (fp16 acc) — reuse Af registers
#pragma unroll
            for (int mt = 0; mt < 4; mt++) {
                uint32_t off = kb + (uint32_t)(mt * 16 * SROW * 2);
                LDSM_X4(Af[mt][0], Af[mt][1], Af[mt][2], Af[mt][3], aLoB + off);
            }
#pragma unroll
            for (int mt = 0; mt < 4; mt++)
#pragma unroll
                for (int nt = 0; nt < 4; nt++)
                    MMA_F16ACC(accL[mt][nt], Af[mt], Bh[nt]);
        }
    }

#pragma unroll
    for (int mt = 0; mt < 4; mt++) {
#pragma unroll
        for (int nt = 0; nt < 4; nt++) {
            int n = cbase + wn * 32 + nt * 8 + 2 * tig;
            float bz0 = bias[n], bz1 = bias[n + 1];
#pragma unroll
            for (int half = 0; half < 2; half++) {
                int m = rbase + wm * 64 + mt * 16 + gid + half * 8;
                // combine: fp32 hi acc + fp16 lo acc + bias
                __half2 hlp = *reinterpret_cast<__half2*>(&accL[mt][nt][half]);
                float2 lo = __half22float2(hlp);
                float v0 = acc[mt][nt][half * 2]     + lo.x + bz0;
                float v1 = acc[mt][nt][half * 2 + 1] + lo.y + bz1;
                if (which == 1) {
                    *(float2*)&C[(size_t)m * N + n] = make_float2(v0, v1);
                } else {
                    int part = n >> 10;
                    int rr   = n & 1023;
                    int h    = rr >> 6;
                    int d    = rr & 63;
                    int b    = m >> 11;
                    int tt   = m & 2047;
                    int pidx = (((b * N_HEADS + h) * SEQ + tt) * HDIM + d) >> 1;
                    if (part == 0) {
                        v0 *= QSCALE; v1 *= QSCALE;
                        uint32_t hi = h2pack(v0, v1);
                        g_qh[pidx] = hi;
                        g_ql[pidx] = h2pack(v0 - h_lo(hi), v1 - h_hi(hi));
                    } else if (part == 1) {
                        g_kh[pidx] = h2pack(v0, v1);
                    } else {
                        g_vh[pidx] = h2pack(v0, v1);
                    }
                }
            }
        }
    }
}

// ===========================================================================
// fp16x2 tensor-core flash attention (unchanged from R13: QKhi+QKlo fp32-acc,
// PV hi-only; exp2 softmax; cp.async double-buffered K/V; 2 CTAs/SM).
// ===========================================================================
#define QROW 72                         // 64 data + 8 pad f16; 144 B rows
#define KVPLANE (64 * QROW * 2)         // 9216 B
#define KVSTAGE (2 * KVPLANE)           // 18432 B  (K_hi, V_hi)
#define ATTN_SMEM2 (2 * 128 * QROW * 2 + 2 * KVSTAGE)   // 73728 B

__global__ __launch_bounds__(256, 2) void attn_v2()
{
    extern __shared__ char smraw[];
    uint16_t* Qh = (uint16_t*)smraw;                 // [128][QROW]
    uint16_t* Ql = Qh + 128 * QROW;
    uint32_t kvbase = smem_u32(smraw) + 2 * 128 * QROW * 2;

    int t    = threadIdx.x;
    int lane = t & 31;
    int w    = t >> 5;
    int gid  = lane >> 2;
    int tig  = lane & 3;
    int bh   = blockIdx.y;
    int q0   = blockIdx.x * 128;

    const uint4* gkh = (const uint4*)(g_kh + (size_t)bh * SEQ * 32);
    const uint4* gvh = (const uint4*)(g_vh + (size_t)bh * SEQ * 32);

    int ksi[2];
    uint32_t kdo[2];
#pragma unroll
    for (int half = 0; half < 2; half++) {
        int g = t + 256 * half;
        int row = g >> 3, c = g & 7;
        ksi[half] = row * 8 + c;
        kdo[half] = (uint32_t)(row * QROW * 2 + c * 16);
    }

    // prefetch K/V tile 0 while staging Q
#pragma unroll
    for (int half = 0; half < 2; half++) {
        uint32_t d = kvbase + kdo[half];
        cp16(d + 0 * KVPLANE, gkh + ksi[half]);
        cp16(d + 1 * KVPLANE, gvh + ksi[half]);
    }
    CP_COMMIT;

    const uint4* gqh = (const uint4*)(g_qh + ((size_t)bh * SEQ + q0) * 32);
    const uint4* gql = (const uint4*)(g_ql + ((size_t)bh * SEQ + q0) * 32);
#pragma unroll
    for (int i = 0; i < 4; i++) {
        int idx = t + 256 * i;
        int r   = idx >> 3;
        int c4  = (idx & 7) << 2;
        *(uint4*)&Qh[r * QROW + 2 * c4] = gqh[r * 8 + (idx & 7)];
        *(uint4*)&Ql[r * QROW + 2 * c4] = gql[r * 8 + (idx & 7)];
    }
    __syncthreads();

    uint32_t lmA = (uint32_t)((w * 16 + (lane & 15)) * QROW + ((lane >> 4) << 3)) * 2;
    uint32_t qhA = smem_u32(Qh) + lmA;
    uint32_t qlA = smem_u32(Ql) + lmA;
    uint32_t Qfh[4][4], Qfl[4][4];
#pragma unroll
    for (int kt = 0; kt < 4; kt++) {
        LDSM_X4(Qfh[kt][0], Qfh[kt][1], Qfh[kt][2], Qfh[kt][3], qhA + kt * 32);
        LDSM_X4(Qfl[kt][0], Qfl[kt][1], Qfl[kt][2], Qfl[kt][3], qlA + kt * 32);
    }

    uint32_t lmB = (uint32_t)((lane & 15) * QROW + ((lane >> 4) << 3)) * 2;

    float O[8][4];
#pragma unroll
    for (int nt = 0; nt < 8; nt++)
#pragma unroll
        for (int r = 0; r < 4; r++) O[nt][r] = 0.f;
    float m0 = -1e30f, m1 = -1e30f, l0 = 0.f, l1 = 0.f;

    const int ntiles = SEQ / 64;
    for (int jt = 0; jt < ntiles; jt++) {
        CP_WAIT0;
        __syncthreads();

        if (jt + 1 < ntiles) {
            uint32_t nb = kvbase + ((jt + 1) & 1) * KVSTAGE;
            int roff = (jt + 1) * 512;
#pragma unroll
            for (int half = 0; half < 2; half++) {
                int si = ksi[half] + roff;
                uint32_t d = nb + kdo[half];
                cp16(d + 0 * KVPLANE, gkh + si);
                cp16(d + 1 * KVPLANE, gvh + si);
            }
            CP_COMMIT;
        }

        uint32_t kvb = kvbase + (jt & 1) * KVSTAGE;
        uint32_t khB = kvb + lmB;
        uint32_t vhB = kvb + KVPLANE + lmB;

        // ---- S = Q K^T (fp16x2, 2 passes) ----
        float s[8][4];
#pragma unroll
        for (int nt = 0; nt < 8; nt++)
#pragma unroll
            for (int r = 0; r < 4; r++) s[nt][r] = 0.f;

#pragma unroll
        for (int kt = 0; kt < 4; kt++) {
            uint32_t KfH[8][2];
#pragma unroll
            for (int p = 0; p < 4; p++) {
                uint32_t off = (uint32_t)(p * 16 * QROW * 2) + kt * 32;
                uint32_t r0, r1, r2, r3;
                LDSM_X4(r0, r1, r2, r3, khB + off);
                KfH[2 * p][0] = r0; KfH[2 * p + 1][0] = r1;
                KfH[2 * p][1] = r2; KfH[2 * p + 1][1] = r3;
            }
#pragma unroll
            for (int nt = 0; nt < 8; nt++)
                MMA_F16(s[nt], Qfh[kt], KfH[nt]);
#pragma unroll
            for (int nt = 0; nt < 8; nt++)
                MMA_F16(s[nt], Qfl[kt], KfH[nt]);
        }

        // ---- online softmax (exp2; q carries log2e) ----
        float mx0 = s[0][0], mx1 = s[0][2];
#pragma unroll
        for (int nt = 0; nt < 8; nt++) {
            mx0 = fmaxf(mx0, fmaxf(s[nt][0], s[nt][1]));
            mx1 = fmaxf(mx1, fmaxf(s[nt][2], s[nt][3]));
        }
        mx0 = fmaxf(mx0, __shfl_xor_sync(0xffffffffu, mx0, 1));
        mx0 = fmaxf(mx0, __shfl_xor_sync(0xffffffffu, mx0, 2));
        mx1 = fmaxf(mx1, __shfl_xor_sync(0xffffffffu, mx1, 1));
        mx1 = fmaxf(mx1, __shfl_xor_sync(0xffffffffu, mx1, 2));

        float mn0 = fmaxf(m0, mx0), mn1 = fmaxf(m1, mx1);
        float a0 = exp2f(m0 - mn0), a1 = exp2f(m1 - mn1);
        m0 = mn0; m1 = mn1;

        float sum0 = 0.f, sum1 = 0.f;
#pragma unroll
        for (int nt = 0; nt < 8; nt++) {
            s[nt][0] = exp2f(s[nt][0] - mn0);
            s[nt][1] = exp2f(s[nt][1] - mn0);
            s[nt][2] = exp2f(s[nt][2] - mn1);
            s[nt][3] = exp2f(s[nt][3] - mn1);
            sum0 += s[nt][0] + s[nt][1];
            sum1 += s[nt][2] + s[nt][3];
        }
        sum0 += __shfl_xor_sync(0xffffffffu, sum0, 1);
        sum0 += __shfl_xor_sync(0xffffffffu, sum0, 2);
        sum1 += __shfl_xor_sync(0xffffffffu, sum1, 1);
        sum1 += __shfl_xor_sync(0xffffffffu, sum1, 2);
        l0 = l0 * a0 + sum0;
        l1 = l1 * a1 + sum1;

#pragma unroll
        for (int nt = 0; nt < 8; nt++) {
            O[nt][0] *= a0; O[nt][1] *= a0;
            O[nt][2] *= a1; O[nt][3] *= a1;
        }

        // ---- P fragments (fp16 hi only) ----
        uint32_t Pah[4][4];
#pragma unroll
        for (int kt = 0; kt < 4; kt++) {
            int e = 2 * kt, o = 2 * kt + 1;
            Pah[kt][0] = h2pack(s[e][0], s[e][1]);
            Pah[kt][1] = h2pack(s[e][2], s[e][3]);
            Pah[kt][2] = h2pack(s[o][0], s[o][1]);
            Pah[kt][3] = h2pack(s[o][2], s[o][3]);
        }

        // ---- O += P V (fp16, 1 pass, V via ldmatrix.trans) ----
#pragma unroll
        for (int kt = 0; kt < 4; kt++) {
            uint32_t VfH[8][2];
#pragma unroll
            for (int p = 0; p < 4; p++) {
                uint32_t off = (uint32_t)(kt * 16 * QROW * 2) + (uint32_t)(p * 16 * 2);
                uint32_t r0, r1, r2, r3;
                LDSM_X4_T(r0, r1, r2, r3, vhB + off);
                VfH[2 * p][0] = r0; VfH[2 * p][1] = r1;
                VfH[2 * p + 1][0] = r2; VfH[2 * p + 1][1] = r3;
            }
#pragma unroll
            for (int nt = 0; nt < 8; nt++)
                MMA_F16(O[nt], Pah[kt], VfH[nt]);
        }
    }

    // ---- epilogue: normalize, split, write ctx fp16 planes ----
    float inv0 = 1.0f / l0, inv1 = 1.0f / l1;
    int b = bh >> 4, h = bh & 15;
    int r0g = q0 + w * 16 + gid;
    int r1g = r0g + 8;
#pragma unroll
    for (int nt = 0; nt < 8; nt++) {
        int d = nt * 8 + 2 * tig;
        size_t p0 = (size_t)(b * SEQ + r0g) * 512 + ((h * 64 + d) >> 1);
        size_t p1 = (size_t)(b * SEQ + r1g) * 512 + ((h * 64 + d) >> 1);
        float v0 = O[nt][0] * inv0, v1 = O[nt][1] * inv0;
        uint32_t hi = h2pack(v0, v1);
        g_ch[p0] = hi;
        g_cl[p0] = h2pack(v0 - h_lo(hi), v1 - h_hi(hi));
        v0 = O[nt][2] * inv1; v1 = O[nt][3] * inv1;
        hi = h2pack(v0, v1);
        g_ch[p1] = hi;
        g_cl[p1] = h2pack(v0 - h_lo(hi), v1 - h_hi(hi));
    }
}

// ---------------------------------------------------------------------------
extern "C" void kernel_launch(void* const* d_in, const int* in_sizes, int n_in,
                              void* d_out, int out_size)
{
    const float* query = (const float*)d_in[0];   // [4,2048,1024]
    const float* in_w  = (const float*)d_in[1];   // [3072,1024]
    const float* in_b  = (const float*)d_in[2];   // [3072]
    const float* out_w = (const float*)d_in[3];   // [1024,1024]
    const float* out_b = (const float*)d_in[4];   // [1024]
    float* out = (float*)d_out;                   // [4,2048,1024]

    cudaFuncSetAttribute(gemm_v2,
                         cudaFuncAttributeMaxDynamicSharedMemorySize, GEMM_SMEM2);
    cudaFuncSetAttribute(attn_v2,
                         cudaFuncAttributeMaxDynamicSharedMemorySize, ATTN_SMEM2);

    // 0) one-pass fp32 -> fp16 plane splits
    conv_split<<<(M_ROWS * E_DIM / 4) / 256, 256>>>((const float4*)query, 0,
                                                    M_ROWS * E_DIM / 4);
    conv_split<<<(3 * E_DIM * E_DIM / 4) / 256, 256>>>((const float4*)in_w, 1,
                                                       3 * E_DIM * E_DIM / 4);
    conv_split<<<(E_DIM * E_DIM / 4) / 256, 256>>>((const float4*)out_w, 2,
                                                   E_DIM * E_DIM / 4);

    // 1) QKV projection + scatter (q scaled w/ log2e)
    gemm_v2<<<dim3(3 * E_DIM / 128, M_ROWS / 128), 256, GEMM_SMEM2>>>(
        in_b, nullptr, E_DIM, 3 * E_DIM, 0);

    // 2) Tensor-core flash attention -> ctx fp16 planes (2 CTAs/SM)
    attn_v2<<<dim3(SEQ / 128, BH_TOT), 256, ATTN_SMEM2>>>();

    // 3) Output projection -> d_out (fp32)
    gemm_v2<<<dim3(E_DIM / 128, M_ROWS / 128), 256, GEMM_SMEM2>>>(
        out_b, out, E_DIM, E_DIM, 1);
}

// round 16
// speedup vs baseline: 1.4205x; 1.4205x over previous
#include <cuda_runtime.h>
#include <cuda_fp16.h>
#include <cstdint>

// Problem constants
#define E_DIM   1024
#define N_HEADS 16
#define HDIM    64
#define NB      4
#define SEQ     2048
#define BH_TOT  (NB * N_HEADS)   // 64
#define M_ROWS  (NB * SEQ)       // 8192
#define QKV_PAIRS (BH_TOT * SEQ * HDIM / 2)   // 4194304
#define QSCALE 0.18033688011112042f           // 0.125 * log2(e)

// Scratch (device globals). fp16x2-pair planes (hi-only except q).
__device__ uint32_t g_ah[M_ROWS * E_DIM / 2];                             // query hi
__device__ uint32_t g_wh[3 * E_DIM * E_DIM / 2];                          // in_w hi
__device__ uint32_t g_oh[E_DIM * E_DIM / 2];                              // out_w hi
__device__ uint32_t g_ch[M_ROWS * E_DIM / 2];                             // ctx hi
__device__ uint32_t g_qh[QKV_PAIRS], g_ql[QKV_PAIRS];                     // q hi+lo
__device__ uint32_t g_kh[QKV_PAIRS];                                      // K hi
__device__ uint32_t g_vh[QKV_PAIRS];                                      // V hi

// ---- helpers ---------------------------------------------------------------
__device__ __forceinline__ uint32_t smem_u32(const void* p) {
    uint32_t a;
    asm("{ .reg .u64 t; cvta.to.shared.u64 t, %1; cvt.u32.u64 %0, t; }"
        : "=r"(a) : "l"(p));
    return a;
}
__device__ __forceinline__ uint32_t h2pack(float e0, float e1) {
    __half2 h = __floats2half2_rn(e0, e1);
    return *reinterpret_cast<uint32_t*>(&h);
}
__device__ __forceinline__ float h_lo(uint32_t p) {
    return __half2float(__ushort_as_half((unsigned short)(p & 0xffffu)));
}
__device__ __forceinline__ float h_hi(uint32_t p) {
    return __half2float(__ushort_as_half((unsigned short)(p >> 16)));
}

__device__ __forceinline__ void cp16(uint32_t dst, const void* src) {
    asm volatile("cp.async.cg.shared.global [%0], [%1], 16;"
                 :: "r"(dst), "l"(src) : "memory");
}
#define CP_COMMIT asm volatile("cp.async.commit_group;" ::: "memory")
#define CP_WAIT0  asm volatile("cp.async.wait_group 0;" ::: "memory")

#define LDSM_X4(r0, r1, r2, r3, addr)                                        \
    asm volatile("ldmatrix.sync.aligned.m8n8.x4.shared.b16 "                 \
                 "{%0, %1, %2, %3}, [%4];"                                   \
                 : "=r"(r0), "=r"(r1), "=r"(r2), "=r"(r3) : "r"(addr))

#define LDSM_X4_T(r0, r1, r2, r3, addr)                                      \
    asm volatile("ldmatrix.sync.aligned.m8n8.x4.trans.shared.b16 "           \
                 "{%0, %1, %2, %3}, [%4];"                                   \
                 : "=r"(r0), "=r"(r1), "=r"(r2), "=r"(r3) : "r"(addr))

#define MMA_F16(c, a, b)                                                     \
    asm volatile("mma.sync.aligned.m16n8k16.row.col.f32.f16.f16.f32 "        \
                 "{%0, %1, %2, %3}, {%4, %5, %6, %7}, {%8, %9}, "            \
                 "{%0, %1, %2, %3};"                                         \
                 : "+f"((c)[0]), "+f"((c)[1]), "+f"((c)[2]), "+f"((c)[3])    \
                 : "r"((a)[0]), "r"((a)[1]), "r"((a)[2]), "r"((a)[3]),       \
                   "r"((b)[0]), "r"((b)[1]))

// ===========================================================================
// One-pass fp32 -> fp16 (hi plane only).  which 0: query  1: in_w  2: out_w
// ===========================================================================
__global__ __launch_bounds__(256) void conv_split(const float4* __restrict__ src,
                                                  int which, int n4)
{
    int i = blockIdx.x * 256 + threadIdx.x;
    if (i >= n4) return;
    float4 a = src[i];
    uint32_t h01 = h2pack(a.x, a.y), h23 = h2pack(a.z, a.w);
    uint2* hi = (uint2*)(which == 0 ? g_ah : (which == 1 ? g_wh : g_oh));
    hi[i] = make_uint2(h01, h23);
}

// ===========================================================================
// Plain fp16 tensor-core NT GEMM (single pass Ah*Bh, fp32 acc),
// cp.async double buffer, one barrier per chunk.
// which 0: A=g_ah, W=g_wh, QKV-scatter epilogue (q *= QSCALE, q split hi/lo)
// which 1: A=g_ch, W=g_oh, C-store epilogue
// ===========================================================================
#define SROW 40                        // f16 per smem row (32 data + 8 pad)
#define GPLANE (128 * SROW * 2)        // 10240 B
#define GSTAGE (2 * GPLANE)            // 20480 B  (A_hi, B_hi)
#define GEMM_SMEM2 (2 * GSTAGE)        // 40960 B

__global__ __launch_bounds__(256, 2) void gemm_v2(
    const float* __restrict__ bias, float* __restrict__ C,
    int K, int N, int which)
{
    extern __shared__ char smraw[];
    uint32_t sbase = smem_u32(smraw);

    const uint4* Ah = (const uint4*)(which == 0 ? g_ah : g_ch);
    const uint4* Wh = (const uint4*)(which == 0 ? g_wh : g_oh);

    int t    = threadIdx.x;
    int lane = t & 31;
    int wid  = t >> 5;
    int wm   = wid >> 2;
    int wn   = wid & 3;
    int gid  = lane >> 2;
    int tig  = lane & 3;

    int rbase = blockIdx.y * 128;
    int cbase = blockIdx.x * 128;
    int kd8   = K >> 3;

    size_t asi[2], wsi[2];
    uint32_t dso[2];
#pragma unroll
    for (int half = 0; half < 2; half++) {
        int g = t + 256 * half;        // 0..511
        int row = g >> 2, c = g & 3;
        asi[half] = (size_t)(rbase + row) * kd8 + c;
        wsi[half] = (size_t)(cbase + row) * kd8 + c;
        dso[half] = (uint32_t)(row * SROW * 2 + c * 16);
    }

    uint32_t lm_off = (uint32_t)((lane & 15) * SROW + ((lane >> 4) << 3)) * 2;

    float acc[4][4][4];
#pragma unroll
    for (int i = 0; i < 4; i++)
#pragma unroll
        for (int j = 0; j < 4; j++)
#pragma unroll
            for (int r = 0; r < 4; r++) acc[i][j][r] = 0.f;

    const int nch = K / 32;

#pragma unroll
    for (int half = 0; half < 2; half++) {
        uint32_t d = sbase + dso[half];
        cp16(d + 0 * GPLANE, Ah + asi[half]);
        cp16(d + 1 * GPLANE, Wh + wsi[half]);
    }
    CP_COMMIT;

    for (int ch = 0; ch < nch; ch++) {
        CP_WAIT0;
        __syncthreads();

        if (ch + 1 < nch) {
            uint32_t nb = sbase + ((ch + 1) & 1) * GSTAGE;
#pragma unroll
            for (int half = 0; half < 2; half++) {
                size_t sa = asi[half] + (size_t)(ch + 1) * 4;
                size_t sw = wsi[half] + (size_t)(ch + 1) * 4;
                uint32_t d = nb + dso[half];
                cp16(d + 0 * GPLANE, Ah + sa);
                cp16(d + 1 * GPLANE, Wh + sw);
            }
            CP_COMMIT;
        }

        uint32_t stb  = sbase + (ch & 1) * GSTAGE;
        uint32_t aHiB = stb + (uint32_t)(wm * 64 * SROW * 2) + lm_off;
        uint32_t bHiB = stb + GPLANE + (uint32_t)(wn * 32 * SROW * 2) + lm_off;

#pragma unroll
        for (int kk = 0; kk < 2; kk++) {
            uint32_t kb = (uint32_t)(kk * 16 * 2);
            uint32_t Af[4][4], Bh[4][2];
#pragma unroll
            for (int mt = 0; mt < 4; mt++) {
                uint32_t off = kb + (uint32_t)(mt * 16 * SROW * 2);
                LDSM_X4(Af[mt][0], Af[mt][1], Af[mt][2], Af[mt][3], aHiB + off);
            }
#pragma unroll
            for (int nt2 = 0; nt2 < 2; nt2++) {
                uint32_t off = kb + (uint32_t)(nt2 * 16 * SROW * 2);
                uint32_t r0, r1, r2, r3;
                LDSM_X4(r0, r1, r2, r3, bHiB + off);
                Bh[nt2 * 2][0] = r0; Bh[nt2 * 2 + 1][0] = r1;
                Bh[nt2 * 2][1] = r2; Bh[nt2 * 2 + 1][1] = r3;
            }
#pragma unroll
            for (int mt = 0; mt < 4; mt++)
#pragma unroll
                for (int nt = 0; nt < 4; nt++)
                    MMA_F16(acc[mt][nt], Af[mt], Bh[nt]);
        }
    }

#pragma unroll
    for (int mt = 0; mt < 4; mt++) {
#pragma unroll
        for (int nt = 0; nt < 4; nt++) {
            int n = cbase + wn * 32 + nt * 8 + 2 * tig;
            float bz0 = bias[n], bz1 = bias[n + 1];
#pragma unroll
            for (int half = 0; half < 2; half++) {
                int m = rbase + wm * 64 + mt * 16 + gid + half * 8;
                float v0 = acc[mt][nt][half * 2]     + bz0;
                float v1 = acc[mt][nt][half * 2 + 1] + bz1;
                if (which == 1) {
                    *(float2*)&C[(size_t)m * N + n] = make_float2(v0, v1);
                } else {
                    int part = n >> 10;
                    int rr   = n & 1023;
                    int h    = rr >> 6;
                    int d    = rr & 63;
                    int b    = m >> 11;
                    int tt   = m & 2047;
                    int pidx = (((b * N_HEADS + h) * SEQ + tt) * HDIM + d) >> 1;
                    if (part == 0) {
                        v0 *= QSCALE; v1 *= QSCALE;
                        uint32_t hi = h2pack(v0, v1);
                        g_qh[pidx] = hi;
                        g_ql[pidx] = h2pack(v0 - h_lo(hi), v1 - h_hi(hi));
                    } else if (part == 1) {
                        g_kh[pidx] = h2pack(v0, v1);
                    } else {
                        g_vh[pidx] = h2pack(v0, v1);
                    }
                }
            }
        }
    }
}

// ===========================================================================
// fp16x2 tensor-core flash attention (R13 structure: QKhi+QKlo fp32-acc,
// PV hi-only; exp2 softmax; cp.async double-buffered K/V; 2 CTAs/SM).
// Epilogue writes ctx hi plane only.
// ===========================================================================
#define QROW 72                         // 64 data + 8 pad f16; 144 B rows
#define KVPLANE (64 * QROW * 2)         // 9216 B
#define KVSTAGE (2 * KVPLANE)           // 18432 B  (K_hi, V_hi)
#define ATTN_SMEM2 (2 * 128 * QROW * 2 + 2 * KVSTAGE)   // 73728 B

__global__ __launch_bounds__(256, 2) void attn_v2()
{
    extern __shared__ char smraw[];
    uint16_t* Qh = (uint16_t*)smraw;                 // [128][QROW]
    uint16_t* Ql = Qh + 128 * QROW;
    uint32_t kvbase = smem_u32(smraw) + 2 * 128 * QROW * 2;

    int t    = threadIdx.x;
    int lane = t & 31;
    int w    = t >> 5;
    int gid  = lane >> 2;
    int tig  = lane & 3;
    int bh   = blockIdx.y;
    int q0   = blockIdx.x * 128;

    const uint4* gkh = (const uint4*)(g_kh + (size_t)bh * SEQ * 32);
    const uint4* gvh = (const uint4*)(g_vh + (size_t)bh * SEQ * 32);

    int ksi[2];
    uint32_t kdo[2];
#pragma unroll
    for (int half = 0; half < 2; half++) {
        int g = t + 256 * half;
        int row = g >> 3, c = g & 7;
        ksi[half] = row * 8 + c;
        kdo[half] = (uint32_t)(row * QROW * 2 + c * 16);
    }

    // prefetch K/V tile 0 while staging Q
#pragma unroll
    for (int half = 0; half < 2; half++) {
        uint32_t d = kvbase + kdo[half];
        cp16(d + 0 * KVPLANE, gkh + ksi[half]);
        cp16(d + 1 * KVPLANE, gvh + ksi[half]);
    }
    CP_COMMIT;

    const uint4* gqh = (const uint4*)(g_qh + ((size_t)bh * SEQ + q0) * 32);
    const uint4* gql = (const uint4*)(g_ql + ((size_t)bh * SEQ + q0) * 32);
#pragma unroll
    for (int i = 0; i < 4; i++) {
        int idx = t + 256 * i;
        int r   = idx >> 3;
        int c4  = (idx & 7) << 2;
        *(uint4*)&Qh[r * QROW + 2 * c4] = gqh[r * 8 + (idx & 7)];
        *(uint4*)&Ql[r * QROW + 2 * c4] = gql[r * 8 + (idx & 7)];
    }
    __syncthreads();

    uint32_t lmA = (uint32_t)((w * 16 + (lane & 15)) * QROW + ((lane >> 4) << 3)) * 2;
    uint32_t qhA = smem_u32(Qh) + lmA;
    uint32_t qlA = smem_u32(Ql) + lmA;
    uint32_t Qfh[4][4], Qfl[4][4];
#pragma unroll
    for (int kt = 0; kt < 4; kt++) {
        LDSM_X4(Qfh[kt][0], Qfh[kt][1], Qfh[kt][2], Qfh[kt][3], qhA + kt * 32);
        LDSM_X4(Qfl[kt][0], Qfl[kt][1], Qfl[kt][2], Qfl[kt][3], qlA + kt * 32);
    }

    uint32_t lmB = (uint32_t)((lane & 15) * QROW + ((lane >> 4) << 3)) * 2;

    float O[8][4];
#pragma unroll
    for (int nt = 0; nt < 8; nt++)
#pragma unroll
        for (int r = 0; r < 4; r++) O[nt][r] = 0.f;
    float m0 = -1e30f, m1 = -1e30f, l0 = 0.f, l1 = 0.f;

    const int ntiles = SEQ / 64;
    for (int jt = 0; jt < ntiles; jt++) {
        CP_WAIT0;
        __syncthreads();

        if (jt + 1 < ntiles) {
            uint32_t nb = kvbase + ((jt + 1) & 1) * KVSTAGE;
            int roff = (jt + 1) * 512;
#pragma unroll
            for (int half = 0; half < 2; half++) {
                int si = ksi[half] + roff;
                uint32_t d = nb + kdo[half];
                cp16(d + 0 * KVPLANE, gkh + si);
                cp16(d + 1 * KVPLANE, gvh + si);
            }
            CP_COMMIT;
        }

        uint32_t kvb = kvbase + (jt & 1) * KVSTAGE;
        uint32_t khB = kvb + lmB;
        uint32_t vhB = kvb + KVPLANE + lmB;

        // ---- S = Q K^T (fp16x2, 2 passes) ----
        float s[8][4];
#pragma unroll
        for (int nt = 0; nt < 8; nt++)
#pragma unroll
            for (int r = 0; r < 4; r++) s[nt][r] = 0.f;

#pragma unroll
        for (int kt = 0; kt < 4; kt++) {
            uint32_t KfH[8][2];
#pragma unroll
            for (int p = 0; p < 4; p++) {
                uint32_t off = (uint32_t)(p * 16 * QROW * 2) + kt * 32;
                uint32_t r0, r1, r2, r3;
                LDSM_X4(r0, r1, r2, r3, khB + off);
                KfH[2 * p][0] = r0; KfH[2 * p + 1][0] = r1;
                KfH[2 * p][1] = r2; KfH[2 * p + 1][1] = r3;
            }
#pragma unroll
            for (int nt = 0; nt < 8; nt++)
                MMA_F16(s[nt], Qfh[kt], KfH[nt]);
#pragma unroll
            for (int nt = 0; nt < 8; nt++)
                MMA_F16(s[nt], Qfl[kt], KfH[nt]);
        }

        // ---- online softmax (exp2; q carries log2e) ----
        float mx0 = s[0][0], mx1 = s[0][2];
#pragma unroll
        for (int nt = 0; nt < 8; nt++) {
            mx0 = fmaxf(mx0, fmaxf(s[nt][0], s[nt][1]));
            mx1 = fmaxf(mx1, fmaxf(s[nt][2], s[nt][3]));
        }
        mx0 = fmaxf(mx0, __shfl_xor_sync(0xffffffffu, mx0, 1));
        mx0 = fmaxf(mx0, __shfl_xor_sync(0xffffffffu, mx0, 2));
        mx1 = fmaxf(mx1, __shfl_xor_sync(0xffffffffu, mx1, 1));
        mx1 = fmaxf(mx1, __shfl_xor_sync(0xffffffffu, mx1, 2));

        float mn0 = fmaxf(m0, mx0), mn1 = fmaxf(m1, mx1);
        float a0 = exp2f(m0 - mn0), a1 = exp2f(m1 - mn1);
        m0 = mn0; m1 = mn1;

        float sum0 = 0.f, sum1 = 0.f;
#pragma unroll
        for (int nt = 0; nt < 8; nt++) {
            s[nt][0] = exp2f(s[nt][0] - mn0);
            s[nt][1] = exp2f(s[nt][1] - mn0);
            s[nt][2] = exp2f(s[nt][2] - mn1);
            s[nt][3] = exp2f(s[nt][3] - mn1);
            sum0 += s[nt][0] + s[nt][1];
            sum1 += s[nt][2] + s[nt][3];
        }
        sum0 += __shfl_xor_sync(0xffffffffu, sum0, 1);
        sum0 += __shfl_xor_sync(0xffffffffu, sum0, 2);
        sum1 += __shfl_xor_sync(0xffffffffu, sum1, 1);
        sum1 += __shfl_xor_sync(0xffffffffu, sum1, 2);
        l0 = l0 * a0 + sum0;
        l1 = l1 * a1 + sum1;

#pragma unroll
        for (int nt = 0; nt < 8; nt++) {
            O[nt][0] *= a0; O[nt][1] *= a0;
            O[nt][2] *= a1; O[nt][3] *= a1;
        }

        // ---- P fragments (fp16 hi only) ----
        uint32_t Pah[4][4];
#pragma unroll
        for (int kt = 0; kt < 4; kt++) {
            int e = 2 * kt, o = 2 * kt + 1;
            Pah[kt][0] = h2pack(s[e][0], s[e][1]);
            Pah[kt][1] = h2pack(s[e][2], s[e][3]);
            Pah[kt][2] = h2pack(s[o][0], s[o][1]);
            Pah[kt][3] = h2pack(s[o][2], s[o][3]);
        }

        // ---- O += P V (fp16, 1 pass, V via ldmatrix.trans) ----
#pragma unroll
        for (int kt = 0; kt < 4; kt++) {
            uint32_t VfH[8][2];
#pragma unroll
            for (int p = 0; p < 4; p++) {
                uint32_t off = (uint32_t)(kt * 16 * QROW * 2) + (uint32_t)(p * 16 * 2);
                uint32_t r0, r1, r2, r3;
                LDSM_X4_T(r0, r1, r2, r3, vhB + off);
                VfH[2 * p][0] = r0; VfH[2 * p][1] = r1;
                VfH[2 * p + 1][0] = r2; VfH[2 * p + 1][1] = r3;
            }
#pragma unroll
            for (int nt = 0; nt < 8; nt++)
                MMA_F16(O[nt], Pah[kt], VfH[nt]);
        }
    }

    // ---- epilogue: normalize, write ctx hi plane only ----
    float inv0 = 1.0f / l0, inv1 = 1.0f / l1;
    int b = bh >> 4, h = bh & 15;
    int r0g = q0 + w * 16 + gid;
    int r1g = r0g + 8;
#pragma unroll
    for (int nt = 0; nt < 8; nt++) {
        int d = nt * 8 + 2 * tig;
        size_t p0 = (size_t)(b * SEQ + r0g) * 512 + ((h * 64 + d) >> 1);
        size_t p1 = (size_t)(b * SEQ + r1g) * 512 + ((h * 64 + d) >> 1);
        g_ch[p0] = h2pack(O[nt][0] * inv0, O[nt][1] * inv0);
        g_ch[p1] = h2pack(O[nt][2] * inv1, O[nt][3] * inv1);
    }
}

// ---------------------------------------------------------------------------
extern "C" void kernel_launch(void* const* d_in, const int* in_sizes, int n_in,
                              void* d_out, int out_size)
{
    const float* query = (const float*)d_in[0];   // [4,2048,1024]
    const float* in_w  = (const float*)d_in[1];   // [3072,1024]
    const float* in_b  = (const float*)d_in[2];   // [3072]
    const float* out_w = (const float*)d_in[3];   // [1024,1024]
    const float* out_b = (const float*)d_in[4];   // [1024]
    float* out = (float*)d_out;                   // [4,2048,1024]

    cudaFuncSetAttribute(gemm_v2,
                         cudaFuncAttributeMaxDynamicSharedMemorySize, GEMM_SMEM2);
    cudaFuncSetAttribute(attn_v2,
                         cudaFuncAttributeMaxDynamicSharedMemorySize, ATTN_SMEM2);

    // 0) one-pass fp32 -> fp16 conversions (hi planes)
    conv_split<<<(M_ROWS * E_DIM / 4) / 256, 256>>>((const float4*)query, 0,
                                                    M_ROWS * E_DIM / 4);
    conv_split<<<(3 * E_DIM * E_DIM / 4) / 256, 256>>>((const float4*)in_w, 1,
                                                       3 * E_DIM * E_DIM / 4);
    conv_split<<<(E_DIM * E_DIM / 4) / 256, 256>>>((const float4*)out_w, 2,
                                                   E_DIM * E_DIM / 4);

    // 1) QKV projection + scatter (q scaled w/ log2e, split hi/lo)
    gemm_v2<<<dim3(3 * E_DIM / 128, M_ROWS / 128), 256, GEMM_SMEM2>>>(
        in_b, nullptr, E_DIM, 3 * E_DIM, 0);

    // 2) Tensor-core flash attention -> ctx hi plane (2 CTAs/SM)
    attn_v2<<<dim3(SEQ / 128, BH_TOT), 256, ATTN_SMEM2>>>();

    // 3) Output projection -> d_out (fp32)
    gemm_v2<<<dim3(E_DIM / 128, M_ROWS / 128), 256, GEMM_SMEM2>>>(
        out_b, out, E_DIM, E_DIM, 1);
}

// round 17
// speedup vs baseline: 1.5662x; 1.1026x over previous
#include <cuda_runtime.h>
#include <cuda_fp16.h>
#include <cstdint>

// Problem constants
#define E_DIM   1024
#define N_HEADS 16
#define HDIM    64
#define NB      4
#define SEQ     2048
#define BH_TOT  (NB * N_HEADS)   // 64
#define M_ROWS  (NB * SEQ)       // 8192
#define QKV_PAIRS (BH_TOT * SEQ * HDIM / 2)   // 4194304
#define QSCALE 0.18033688011112042f           // 0.125 * log2(e)

// Scratch (device globals). fp16x2-pair planes, hi-only everywhere.
__device__ uint32_t g_ah[M_ROWS * E_DIM / 2];                             // query hi
__device__ uint32_t g_wh[3 * E_DIM * E_DIM / 2];                          // in_w hi
__device__ uint32_t g_oh[E_DIM * E_DIM / 2];                              // out_w hi
__device__ uint32_t g_ch[M_ROWS * E_DIM / 2];                             // ctx hi
__device__ uint32_t g_qh[QKV_PAIRS];                                      // q hi
__device__ uint32_t g_kh[QKV_PAIRS];                                      // K hi
__device__ uint32_t g_vh[QKV_PAIRS];                                      // V hi

// ---- helpers ---------------------------------------------------------------
__device__ __forceinline__ uint32_t smem_u32(const void* p) {
    uint32_t a;
    asm("{ .reg .u64 t; cvta.to.shared.u64 t, %1; cvt.u32.u64 %0, t; }"
        : "=r"(a) : "l"(p));
    return a;
}
__device__ __forceinline__ uint32_t h2pack(float e0, float e1) {
    __half2 h = __floats2half2_rn(e0, e1);
    return *reinterpret_cast<uint32_t*>(&h);
}

__device__ __forceinline__ void cp16(uint32_t dst, const void* src) {
    asm volatile("cp.async.cg.shared.global [%0], [%1], 16;"
                 :: "r"(dst), "l"(src) : "memory");
}
#define CP_COMMIT asm volatile("cp.async.commit_group;" ::: "memory")
#define CP_WAIT0  asm volatile("cp.async.wait_group 0;" ::: "memory")

#define LDSM_X4(r0, r1, r2, r3, addr)                                        \
    asm volatile("ldmatrix.sync.aligned.m8n8.x4.shared.b16 "                 \
                 "{%0, %1, %2, %3}, [%4];"                                   \
                 : "=r"(r0), "=r"(r1), "=r"(r2), "=r"(r3) : "r"(addr))

#define LDSM_X4_T(r0, r1, r2, r3, addr)                                      \
    asm volatile("ldmatrix.sync.aligned.m8n8.x4.trans.shared.b16 "           \
                 "{%0, %1, %2, %3}, [%4];"                                   \
                 : "=r"(r0), "=r"(r1), "=r"(r2), "=r"(r3) : "r"(addr))

#define MMA_F16(c, a, b)                                                     \
    asm volatile("mma.sync.aligned.m16n8k16.row.col.f32.f16.f16.f32 "        \
                 "{%0, %1, %2, %3}, {%4, %5, %6, %7}, {%8, %9}, "            \
                 "{%0, %1, %2, %3};"                                         \
                 : "+f"((c)[0]), "+f"((c)[1]), "+f"((c)[2]), "+f"((c)[3])    \
                 : "r"((a)[0]), "r"((a)[1]), "r"((a)[2]), "r"((a)[3]),       \
                   "r"((b)[0]), "r"((b)[1]))

// ===========================================================================
// One-pass fp32 -> fp16 (hi plane only).  which 0: query  1: in_w  2: out_w
// ===========================================================================
__global__ __launch_bounds__(256) void conv_split(const float4* __restrict__ src,
                                                  int which, int n4)
{
    int i = blockIdx.x * 256 + threadIdx.x;
    if (i >= n4) return;
    float4 a = src[i];
    uint32_t h01 = h2pack(a.x, a.y), h23 = h2pack(a.z, a.w);
    uint2* hi = (uint2*)(which == 0 ? g_ah : (which == 1 ? g_wh : g_oh));
    hi[i] = make_uint2(h01, h23);
}

// ===========================================================================
// Plain fp16 tensor-core NT GEMM (single pass Ah*Bh, fp32 acc),
// cp.async double buffer, one barrier per chunk.
// which 0: A=g_ah, W=g_wh, QKV-scatter epilogue (q *= QSCALE)
// which 1: A=g_ch, W=g_oh, C-store epilogue
// ===========================================================================
#define SROW 40                        // f16 per smem row (32 data + 8 pad)
#define GPLANE (128 * SROW * 2)        // 10240 B
#define GSTAGE (2 * GPLANE)            // 20480 B  (A_hi, B_hi)
#define GEMM_SMEM2 (2 * GSTAGE)        // 40960 B

__global__ __launch_bounds__(256, 2) void gemm_v2(
    const float* __restrict__ bias, float* __restrict__ C,
    int K, int N, int which)
{
    extern __shared__ char smraw[];
    uint32_t sbase = smem_u32(smraw);

    const uint4* Ah = (const uint4*)(which == 0 ? g_ah : g_ch);
    const uint4* Wh = (const uint4*)(which == 0 ? g_wh : g_oh);

    int t    = threadIdx.x;
    int lane = t & 31;
    int wid  = t >> 5;
    int wm   = wid >> 2;
    int wn   = wid & 3;
    int gid  = lane >> 2;
    int tig  = lane & 3;

    int rbase = blockIdx.y * 128;
    int cbase = blockIdx.x * 128;
    int kd8   = K >> 3;

    size_t asi[2], wsi[2];
    uint32_t dso[2];
#pragma unroll
    for (int half = 0; half < 2; half++) {
        int g = t + 256 * half;        // 0..511
        int row = g >> 2, c = g & 3;
        asi[half] = (size_t)(rbase + row) * kd8 + c;
        wsi[half] = (size_t)(cbase + row) * kd8 + c;
        dso[half] = (uint32_t)(row * SROW * 2 + c * 16);
    }

    uint32_t lm_off = (uint32_t)((lane & 15) * SROW + ((lane >> 4) << 3)) * 2;

    float acc[4][4][4];
#pragma unroll
    for (int i = 0; i < 4; i++)
#pragma unroll
        for (int j = 0; j < 4; j++)
#pragma unroll
            for (int r = 0; r < 4; r++) acc[i][j][r] = 0.f;

    const int nch = K / 32;

#pragma unroll
    for (int half = 0; half < 2; half++) {
        uint32_t d = sbase + dso[half];
        cp16(d + 0 * GPLANE, Ah + asi[half]);
        cp16(d + 1 * GPLANE, Wh + wsi[half]);
    }
    CP_COMMIT;

    for (int ch = 0; ch < nch; ch++) {
        CP_WAIT0;
        __syncthreads();

        if (ch + 1 < nch) {
            uint32_t nb = sbase + ((ch + 1) & 1) * GSTAGE;
#pragma unroll
            for (int half = 0; half < 2; half++) {
                size_t sa = asi[half] + (size_t)(ch + 1) * 4;
                size_t sw = wsi[half] + (size_t)(ch + 1) * 4;
                uint32_t d = nb + dso[half];
                cp16(d + 0 * GPLANE, Ah + sa);
                cp16(d + 1 * GPLANE, Wh + sw);
            }
            CP_COMMIT;
        }

        uint32_t stb  = sbase + (ch & 1) * GSTAGE;
        uint32_t aHiB = stb + (uint32_t)(wm * 64 * SROW * 2) + lm_off;
        uint32_t bHiB = stb + GPLANE + (uint32_t)(wn * 32 * SROW * 2) + lm_off;

#pragma unroll
        for (int kk = 0; kk < 2; kk++) {
            uint32_t kb = (uint32_t)(kk * 16 * 2);
            uint32_t Af[4][4], Bh[4][2];
#pragma unroll
            for (int mt = 0; mt < 4; mt++) {
                uint32_t off = kb + (uint32_t)(mt * 16 * SROW * 2);
                LDSM_X4(Af[mt][0], Af[mt][1], Af[mt][2], Af[mt][3], aHiB + off);
            }
#pragma unroll
            for (int nt2 = 0; nt2 < 2; nt2++) {
                uint32_t off = kb + (uint32_t)(nt2 * 16 * SROW * 2);
                uint32_t r0, r1, r2, r3;
                LDSM_X4(r0, r1, r2, r3, bHiB + off);
                Bh[nt2 * 2][0] = r0; Bh[nt2 * 2 + 1][0] = r1;
                Bh[nt2 * 2][1] = r2; Bh[nt2 * 2 + 1][1] = r3;
            }
#pragma unroll
            for (int mt = 0; mt < 4; mt++)
#pragma unroll
                for (int nt = 0; nt < 4; nt++)
                    MMA_F16(acc[mt][nt], Af[mt], Bh[nt]);
        }
    }

#pragma unroll
    for (int mt = 0; mt < 4; mt++) {
#pragma unroll
        for (int nt = 0; nt < 4; nt++) {
            int n = cbase + wn * 32 + nt * 8 + 2 * tig;
            float bz0 = bias[n], bz1 = bias[n + 1];
#pragma unroll
            for (int half = 0; half < 2; half++) {
                int m = rbase + wm * 64 + mt * 16 + gid + half * 8;
                float v0 = acc[mt][nt][half * 2]     + bz0;
                float v1 = acc[mt][nt][half * 2 + 1] + bz1;
                if (which == 1) {
                    *(float2*)&C[(size_t)m * N + n] = make_float2(v0, v1);
                } else {
                    int part = n >> 10;
                    int rr   = n & 1023;
                    int h    = rr >> 6;
                    int d    = rr & 63;
                    int b    = m >> 11;
                    int tt   = m & 2047;
                    int pidx = (((b * N_HEADS + h) * SEQ + tt) * HDIM + d) >> 1;
                    if (part == 0) {
                        g_qh[pidx] = h2pack(v0 * QSCALE, v1 * QSCALE);
                    } else if (part == 1) {
                        g_kh[pidx] = h2pack(v0, v1);
                    } else {
                        g_vh[pidx] = h2pack(v0, v1);
                    }
                }
            }
        }
    }
}

// ===========================================================================
// fp16 tensor-core flash attention, single-pass QK and PV; exp2 softmax;
// cp.async double-buffered K/V; 2 CTAs/SM.
// ===========================================================================
#define QROW 72                         // 64 data + 8 pad f16; 144 B rows
#define KVPLANE (64 * QROW * 2)         // 9216 B
#define KVSTAGE (2 * KVPLANE)           // 18432 B  (K_hi, V_hi)
#define ATTN_SMEM2 (128 * QROW * 2 + 2 * KVSTAGE)   // 55296 B

__global__ __launch_bounds__(256, 2) void attn_v2()
{
    extern __shared__ char smraw[];
    uint16_t* Qh = (uint16_t*)smraw;                 // [128][QROW]
    uint32_t kvbase = smem_u32(smraw) + 128 * QROW * 2;

    int t    = threadIdx.x;
    int lane = t & 31;
    int w    = t >> 5;
    int gid  = lane >> 2;
    int tig  = lane & 3;
    int bh   = blockIdx.y;
    int q0   = blockIdx.x * 128;

    const uint4* gkh = (const uint4*)(g_kh + (size_t)bh * SEQ * 32);
    const uint4* gvh = (const uint4*)(g_vh + (size_t)bh * SEQ * 32);

    int ksi[2];
    uint32_t kdo[2];
#pragma unroll
    for (int half = 0; half < 2; half++) {
        int g = t + 256 * half;
        int row = g >> 3, c = g & 7;
        ksi[half] = row * 8 + c;
        kdo[half] = (uint32_t)(row * QROW * 2 + c * 16);
    }

    // prefetch K/V tile 0 while staging Q
#pragma unroll
    for (int half = 0; half < 2; half++) {
        uint32_t d = kvbase + kdo[half];
        cp16(d + 0 * KVPLANE, gkh + ksi[half]);
        cp16(d + 1 * KVPLANE, gvh + ksi[half]);
    }
    CP_COMMIT;

    const uint4* gqh = (const uint4*)(g_qh + ((size_t)bh * SEQ + q0) * 32);
#pragma unroll
    for (int i = 0; i < 4; i++) {
        int idx = t + 256 * i;
        int r   = idx >> 3;
        int c4  = (idx & 7) << 2;
        *(uint4*)&Qh[r * QROW + 2 * c4] = gqh[r * 8 + (idx & 7)];
    }
    __syncthreads();

    uint32_t lmA = (uint32_t)((w * 16 + (lane & 15)) * QROW + ((lane >> 4) << 3)) * 2;
    uint32_t qhA = smem_u32(Qh) + lmA;
    uint32_t Qfh[4][4];
#pragma unroll
    for (int kt = 0; kt < 4; kt++)
        LDSM_X4(Qfh[kt][0], Qfh[kt][1], Qfh[kt][2], Qfh[kt][3], qhA + kt * 32);

    uint32_t lmB = (uint32_t)((lane & 15) * QROW + ((lane >> 4) << 3)) * 2;

    float O[8][4];
#pragma unroll
    for (int nt = 0; nt < 8; nt++)
#pragma unroll
        for (int r = 0; r < 4; r++) O[nt][r] = 0.f;
    float m0 = -1e30f, m1 = -1e30f, l0 = 0.f, l1 = 0.f;

    const int ntiles = SEQ / 64;
    for (int jt = 0; jt < ntiles; jt++) {
        CP_WAIT0;
        __syncthreads();

        if (jt + 1 < ntiles) {
            uint32_t nb = kvbase + ((jt + 1) & 1) * KVSTAGE;
            int roff = (jt + 1) * 512;
#pragma unroll
            for (int half = 0; half < 2; half++) {
                int si = ksi[half] + roff;
                uint32_t d = nb + kdo[half];
                cp16(d + 0 * KVPLANE, gkh + si);
                cp16(d + 1 * KVPLANE, gvh + si);
            }
            CP_COMMIT;
        }

        uint32_t kvb = kvbase + (jt & 1) * KVSTAGE;
        uint32_t khB = kvb + lmB;
        uint32_t vhB = kvb + KVPLANE + lmB;

        // ---- S = Q K^T (fp16, single pass) ----
        float s[8][4];
#pragma unroll
        for (int nt = 0; nt < 8; nt++)
#pragma unroll
            for (int r = 0; r < 4; r++) s[nt][r] = 0.f;

#pragma unroll
        for (int kt = 0; kt < 4; kt++) {
            uint32_t KfH[8][2];
#pragma unroll
            for (int p = 0; p < 4; p++) {
                uint32_t off = (uint32_t)(p * 16 * QROW * 2) + kt * 32;
                uint32_t r0, r1, r2, r3;
                LDSM_X4(r0, r1, r2, r3, khB + off);
                KfH[2 * p][0] = r0; KfH[2 * p + 1][0] = r1;
                KfH[2 * p][1] = r2; KfH[2 * p + 1][1] = r3;
            }
#pragma unroll
            for (int nt = 0; nt < 8; nt++)
                MMA_F16(s[nt], Qfh[kt], KfH[nt]);
        }

        // ---- online softmax (exp2; q carries log2e) ----
        float mx0 = s[0][0], mx1 = s[0][2];
#pragma unroll
        for (int nt = 0; nt < 8; nt++) {
            mx0 = fmaxf(mx0, fmaxf(s[nt][0], s[nt][1]));
            mx1 = fmaxf(mx1, fmaxf(s[nt][2], s[nt][3]));
        }
        mx0 = fmaxf(mx0, __shfl_xor_sync(0xffffffffu, mx0, 1));
        mx0 = fmaxf(mx0, __shfl_xor_sync(0xffffffffu, mx0, 2));
        mx1 = fmaxf(mx1, __shfl_xor_sync(0xffffffffu, mx1, 1));
        mx1 = fmaxf(mx1, __shfl_xor_sync(0xffffffffu, mx1, 2));

        float mn0 = fmaxf(m0, mx0), mn1 = fmaxf(m1, mx1);
        float a0 = exp2f(m0 - mn0), a1 = exp2f(m1 - mn1);
        m0 = mn0; m1 = mn1;

        float sum0 = 0.f, sum1 = 0.f;
#pragma unroll
        for (int nt = 0; nt < 8; nt++) {
            s[nt][0] = exp2f(s[nt][0] - mn0);
            s[nt][1] = exp2f(s[nt][1] - mn0);
            s[nt][2] = exp2f(s[nt][2] - mn1);
            s[nt][3] = exp2f(s[nt][3] - mn1);
            sum0 += s[nt][0] + s[nt][1];
            sum1 += s[nt][2] + s[nt][3];
        }
        sum0 += __shfl_xor_sync(0xffffffffu, sum0, 1);
        sum0 += __shfl_xor_sync(0xffffffffu, sum0, 2);
        sum1 += __shfl_xor_sync(0xffffffffu, sum1, 1);
        sum1 += __shfl_xor_sync(0xffffffffu, sum1, 2);
        l0 = l0 * a0 + sum0;
        l1 = l1 * a1 + sum1;

#pragma unroll
        for (int nt = 0; nt < 8; nt++) {
            O[nt][0] *= a0; O[nt][1] *= a0;
            O[nt][2] *= a1; O[nt][3] *= a1;
        }

        // ---- P fragments (fp16 hi) ----
        uint32_t Pah[4][4];
#pragma unroll
        for (int kt = 0; kt < 4; kt++) {
            int e = 2 * kt, o = 2 * kt + 1;
            Pah[kt][0] = h2pack(s[e][0], s[e][1]);
            Pah[kt][1] = h2pack(s[e][2], s[e][3]);
            Pah[kt][2] = h2pack(s[o][0], s[o][1]);
            Pah[kt][3] = h2pack(s[o][2], s[o][3]);
        }

        // ---- O += P V (fp16, 1 pass, V via ldmatrix.trans) ----
#pragma unroll
        for (int kt = 0; kt < 4; kt++) {
            uint32_t VfH[8][2];
#pragma unroll
            for (int p = 0; p < 4; p++) {
                uint32_t off = (uint32_t)(kt * 16 * QROW * 2) + (uint32_t)(p * 16 * 2);
                uint32_t r0, r1, r2, r3;
                LDSM_X4_T(r0, r1, r2, r3, vhB + off);
                VfH[2 * p][0] = r0; VfH[2 * p][1] = r1;
                VfH[2 * p + 1][0] = r2; VfH[2 * p + 1][1] = r3;
            }
#pragma unroll
            for (int nt = 0; nt < 8; nt++)
                MMA_F16(O[nt], Pah[kt], VfH[nt]);
        }
    }

    // ---- epilogue: normalize, write ctx hi plane ----
    float inv0 = 1.0f / l0, inv1 = 1.0f / l1;
    int b = bh >> 4, h = bh & 15;
    int r0g = q0 + w * 16 + gid;
    int r1g = r0g + 8;
#pragma unroll
    for (int nt = 0; nt < 8; nt++) {
        int d = nt * 8 + 2 * tig;
        size_t p0 = (size_t)(b * SEQ + r0g) * 512 + ((h * 64 + d) >> 1);
        size_t p1 = (size_t)(b * SEQ + r1g) * 512 + ((h * 64 + d) >> 1);
        g_ch[p0] = h2pack(O[nt][0] * inv0, O[nt][1] * inv0);
        g_ch[p1] = h2pack(O[nt][2] * inv1, O[nt][3] * inv1);
    }
}

// ---------------------------------------------------------------------------
extern "C" void kernel_launch(void* const* d_in, const int* in_sizes, int n_in,
                              void* d_out, int out_size)
{
    const float* query = (const float*)d_in[0];   // [4,2048,1024]
    const float* in_w  = (const float*)d_in[1];   // [3072,1024]
    const float* in_b  = (const float*)d_in[2];   // [3072]
    const float* out_w = (const float*)d_in[3];   // [1024,1024]
    const float* out_b = (const float*)d_in[4];   // [1024]
    float* out = (float*)d_out;                   // [4,2048,1024]

    cudaFuncSetAttribute(gemm_v2,
                         cudaFuncAttributeMaxDynamicSharedMemorySize, GEMM_SMEM2);
    cudaFuncSetAttribute(attn_v2,
                         cudaFuncAttributeMaxDynamicSharedMemorySize, ATTN_SMEM2);

    // 0) one-pass fp32 -> fp16 conversions (hi planes)
    conv_split<<<(M_ROWS * E_DIM / 4) / 256, 256>>>((const float4*)query, 0,
                                                    M_ROWS * E_DIM / 4);
    conv_split<<<(3 * E_DIM * E_DIM / 4) / 256, 256>>>((const float4*)in_w, 1,
                                                       3 * E_DIM * E_DIM / 4);
    conv_split<<<(E_DIM * E_DIM / 4) / 256, 256>>>((const float4*)out_w, 2,
                                                   E_DIM * E_DIM / 4);

    // 1) QKV projection + scatter (q scaled w/ log2e)
    gemm_v2<<<dim3(3 * E_DIM / 128, M_ROWS / 128), 256, GEMM_SMEM2>>>(
        in_b, nullptr, E_DIM, 3 * E_DIM, 0);

    // 2) Tensor-core flash attention -> ctx hi plane (2 CTAs/SM)
    attn_v2<<<dim3(SEQ / 128, BH_TOT), 256, ATTN_SMEM2>>>();

    // 3) Output projection -> d_out (fp32)
    gemm_v2<<<dim3(E_DIM / 128, M_ROWS / 128), 256, GEMM_SMEM2>>>(
        out_b, out, E_DIM, E_DIM, 1);
}